// round 1
// baseline (speedup 1.0000x reference)
#include <cuda_runtime.h>

// CRPS loss: out = mean|y_pred - y| - sum_{i,k,l}|x[i,k]-x[i,l]| / (n*2*m^2)
// Sorted-row identity: sum over ordered pairs |x_k - x_l| = 2 * sum_j (2j-m+1) x_(j)
// => mix contribution per row = sum_j (2j-m+1) x_(j) / (n*m^2)
//
// Kernel 1: one 256-thread CTA per row. Bitonic sort row in smem, compute
//           mae partial + weighted sorted sum, block-reduce, write per-row
//           partial to device scratch (deterministic, no float atomics).
// Kernel 2: single CTA reduces the 4096 partials into d_out[0].

#define MDIM 256
#define MAX_ROWS 8192

__device__ float g_partials[MAX_ROWS];

__global__ void __launch_bounds__(MDIM) crps_row_kernel(
    const float* __restrict__ y_pred,
    const float* __restrict__ y,
    float c1,   //  1/(n*m)    (mae scale)
    float c2)   // -1/(n*m*m)  (mix scale, negated)
{
    __shared__ float sm[MDIM];
    const int row = blockIdx.x;
    const int tid = threadIdx.x;

    const float x  = y_pred[row * MDIM + tid];
    const float yv = __ldg(&y[row]);
    const float mae = fabsf(x - yv);

    sm[tid] = x;
    __syncthreads();

    // Bitonic sort, ascending, 256 elements, 36 rounds
    #pragma unroll
    for (int k = 2; k <= MDIM; k <<= 1) {
        #pragma unroll
        for (int j = k >> 1; j > 0; j >>= 1) {
            const int ixj = tid ^ j;
            if (ixj > tid) {
                const float a = sm[tid];
                const float b = sm[ixj];
                const bool up = ((tid & k) == 0);
                if ((a > b) == up) { sm[tid] = b; sm[ixj] = a; }
            }
            __syncthreads();
        }
    }

    const float s = sm[tid];
    const float w = (float)(2 * tid - (MDIM - 1));
    float t = mae * c1 + w * s * c2;

    // block reduction
    #pragma unroll
    for (int off = 16; off; off >>= 1)
        t += __shfl_xor_sync(0xffffffffu, t, off);

    __shared__ float red[MDIM / 32];
    if ((tid & 31) == 0) red[tid >> 5] = t;
    __syncthreads();
    if (tid < MDIM / 32) {
        float v = red[tid];
        #pragma unroll
        for (int off = (MDIM / 64); off; off >>= 1)
            v += __shfl_xor_sync((1u << (MDIM / 32)) - 1u, v, off);
        if (tid == 0) g_partials[row] = v;
    }
}

__global__ void __launch_bounds__(256) crps_reduce_kernel(float* __restrict__ out, int n)
{
    const int tid = threadIdx.x;
    float t = 0.0f;
    for (int i = tid; i < n; i += 256) t += g_partials[i];
    #pragma unroll
    for (int off = 16; off; off >>= 1)
        t += __shfl_xor_sync(0xffffffffu, t, off);

    __shared__ float red[8];
    if ((tid & 31) == 0) red[tid >> 5] = t;
    __syncthreads();
    if (tid < 8) {
        float v = red[tid];
        #pragma unroll
        for (int off = 4; off; off >>= 1)
            v += __shfl_xor_sync(0xffu, v, off);
        if (tid == 0) out[0] = v;
    }
}

extern "C" void kernel_launch(void* const* d_in, const int* in_sizes, int n_in,
                              void* d_out, int out_size)
{
    const float* y_pred = (const float*)d_in[0];
    const float* y      = (const float*)d_in[1];
    float* out          = (float*)d_out;

    const int n = in_sizes[1];               // 4096 rows (y has n elements)
    const int m = in_sizes[0] / n;           // 256 ensemble members (== MDIM)
    (void)m; (void)n_in; (void)out_size;

    const float c1 =  1.0f / ((float)n * (float)MDIM);
    const float c2 = -1.0f / ((float)n * (float)MDIM * (float)MDIM);

    crps_row_kernel<<<n, MDIM>>>(y_pred, y, c1, c2);
    crps_reduce_kernel<<<1, 256>>>(out, n);
}

// round 2
// speedup vs baseline: 1.1905x; 1.1905x over previous
#include <cuda_runtime.h>

// CRPS loss: out = mean|y_pred - y| - sum_{i,k,l}|x[i,k]-x[i,l]| / (n*2*m^2)
// Sorted-row identity:  sum_{k,l} |x_k - x_l| = 2 * sum_j (2j - m + 1) * x_(j)
// => per-row contribution = sum_j mae_j/(n*m) - (2j-m+1)*x_(j)/(n*m^2)
//
// One 256-thread CTA per row. Hybrid bitonic sort: strides <32 via shfl_xor
// (no barriers), strides >=32 via shared memory (12 barriers total instead
// of 36). Final scalar reduction fused via last-block-done pattern
// (deterministic: one block sums the fixed-order partial array).

#define MDIM 256
#define MAX_ROWS 8192

__device__ float        g_partials[MAX_ROWS];
__device__ unsigned int g_count;   // zero-initialized; reset by last block each launch

__device__ __forceinline__ float cas_sel(float v, float p, bool up, bool upper) {
    // ascending region: lower index keeps min, upper keeps max
    return (up != upper) ? fminf(v, p) : fmaxf(v, p);
}

__global__ void __launch_bounds__(MDIM) crps_row_kernel(
    const float* __restrict__ y_pred,
    const float* __restrict__ y,
    float c1,   //  1/(n*m)
    float c2,   // -1/(n*m*m)
    float* __restrict__ out,
    int n)
{
    __shared__ float sm[MDIM];
    __shared__ bool  s_last;
    const int row = blockIdx.x;
    const int tid = threadIdx.x;

    float v = y_pred[row * MDIM + tid];
    const float yv  = __ldg(&y[row]);
    const float mae = fabsf(v - yv);

    // ---- bitonic sort, 256 elements, value-per-thread ----
    // Stages k=2..32: stride j<32, pure intra-warp shfl (no barriers).
    #pragma unroll
    for (int k = 2; k <= 32; k <<= 1) {
        const bool up = ((tid & k) == 0);
        #pragma unroll
        for (int j = k >> 1; j > 0; j >>= 1) {
            const float p = __shfl_xor_sync(0xffffffffu, v, j);
            v = cas_sel(v, p, up, (tid & j) != 0);
        }
    }
    // Stages k=64,128,256: strides >=32 via smem, then shfl tail.
    #pragma unroll
    for (int k = 64; k <= MDIM; k <<= 1) {
        const bool up = ((tid & k) == 0);
        #pragma unroll
        for (int j = k >> 1; j >= 32; j >>= 1) {
            sm[tid] = v;
            __syncthreads();
            const float p = sm[tid ^ j];
            __syncthreads();
            v = cas_sel(v, p, up, (tid & j) != 0);
        }
        #pragma unroll
        for (int j = 16; j > 0; j >>= 1) {
            const float p = __shfl_xor_sync(0xffffffffu, v, j);
            v = cas_sel(v, p, up, (tid & j) != 0);
        }
    }

    // ---- per-row weighted sum + block reduction ----
    const float w = (float)(2 * tid - (MDIM - 1));
    float t = mae * c1 + w * v * c2;

    #pragma unroll
    for (int off = 16; off; off >>= 1)
        t += __shfl_xor_sync(0xffffffffu, t, off);

    __shared__ float red[MDIM / 32];
    if ((tid & 31) == 0) red[tid >> 5] = t;
    __syncthreads();
    if (tid == 0) {
        float s = 0.0f;
        #pragma unroll
        for (int i = 0; i < MDIM / 32; i++) s += red[i];
        g_partials[row] = s;
        __threadfence();
        const unsigned int old = atomicAdd(&g_count, 1u);
        s_last = (old == (unsigned int)(n - 1));
    }
    __syncthreads();

    // ---- last block: deterministic final reduction ----
    if (s_last) {
        __threadfence();  // make all g_partials writes visible
        float acc = 0.0f;
        for (int i = tid; i < n; i += MDIM) acc += g_partials[i];
        #pragma unroll
        for (int off = 16; off; off >>= 1)
            acc += __shfl_xor_sync(0xffffffffu, acc, off);
        if ((tid & 31) == 0) red[tid >> 5] = acc;
        __syncthreads();
        if (tid == 0) {
            float s = 0.0f;
            #pragma unroll
            for (int i = 0; i < MDIM / 32; i++) s += red[i];
            out[0] = s;
            g_count = 0;   // reset for next graph replay
        }
    }
}

extern "C" void kernel_launch(void* const* d_in, const int* in_sizes, int n_in,
                              void* d_out, int out_size)
{
    const float* y_pred = (const float*)d_in[0];
    const float* y      = (const float*)d_in[1];
    float* out          = (float*)d_out;

    const int n = in_sizes[1];      // 4096 rows
    (void)n_in; (void)out_size;

    const float c1 =  1.0f / ((float)n * (float)MDIM);
    const float c2 = -1.0f / ((float)n * (float)MDIM * (float)MDIM);

    crps_row_kernel<<<n, MDIM>>>(y_pred, y, c1, c2, out, n);
}

// round 3
// speedup vs baseline: 2.1400x; 1.7975x over previous
#include <cuda_runtime.h>

// CRPS loss: out = mean|y_pred - y| - sum_{i,k,l}|x[i,k]-x[i,l]| / (n*2*m^2)
// Sorted-row identity:  sum_{k,l}|x_k - x_l| = 2 * sum_j (2j - m + 1) x_(j)
//
// One WARP per row, 8 elements per thread (element index = lane*8 + r).
// Bitonic sort: strides 1,2,4 = in-register compare-exchange (FMNMX),
// strides 8..128 = shfl_xor + predicated FMNMX. No __syncthreads in sort.
// CTA = 8 warps = 8 rows. Fused final reduction via last-block-done.

#define MDIM 256
#define VPT 8                  // values per thread
#define ROWS_PER_CTA 8
#define MAX_CTAS 4096

__device__ float        g_partials[MAX_CTAS];
__device__ unsigned int g_count;     // zero-init; reset by last CTA each launch

__device__ __forceinline__ void cex_asc(float& a, float& b) {
    float mn = fminf(a, b); b = fmaxf(a, b); a = mn;
}
__device__ __forceinline__ void cex_desc(float& a, float& b) {
    float mx = fmaxf(a, b); b = fminf(a, b); a = mx;
}
__device__ __forceinline__ void cex_rt(float& a, float& b, bool asc) {
    float mn = fminf(a, b), mx = fmaxf(a, b);
    a = asc ? mn : mx;
    b = asc ? mx : mn;
}

template <int J>
__device__ __forceinline__ void intra_rt(float v[VPT], bool up) {
    #pragma unroll
    for (int r = 0; r < VPT; r++)
        if ((r & J) == 0) cex_rt(v[r], v[r | J], up);
}

template <int LM>
__device__ __forceinline__ void cross(float v[VPT], bool up, int lane) {
    const bool keep_min = (up != ((lane & LM) != 0));
    #pragma unroll
    for (int r = 0; r < VPT; r++) {
        float p = __shfl_xor_sync(0xffffffffu, v[r], LM);
        v[r] = keep_min ? fminf(v[r], p) : fmaxf(v[r], p);
    }
}

__global__ void __launch_bounds__(MDIM) crps_row_kernel(
    const float* __restrict__ y_pred,
    const float* __restrict__ y,
    float c1,   //  1/(n*m)
    float c2,   // -1/(n*m*m)
    float* __restrict__ out,
    int n_ctas)
{
    const int warp = threadIdx.x >> 5;
    const int lane = threadIdx.x & 31;
    const int row  = blockIdx.x * ROWS_PER_CTA + warp;

    // Load 8 contiguous floats per lane (two float4: warp covers the full row)
    const float4* p = (const float4*)(y_pred + row * MDIM + lane * VPT);
    const float4 a4 = p[0];
    const float4 b4 = p[1];
    float v[VPT] = {a4.x, a4.y, a4.z, a4.w, b4.x, b4.y, b4.z, b4.w};

    const float yv = __ldg(&y[row]);
    float mae = 0.0f;
    #pragma unroll
    for (int r = 0; r < VPT; r++) mae += fabsf(v[r] - yv);

    // ---- bitonic sort of 256 elements, warp-collective ----
    // k=2
    cex_asc(v[0], v[1]); cex_desc(v[2], v[3]);
    cex_asc(v[4], v[5]); cex_desc(v[6], v[7]);
    // k=4
    cex_asc(v[0], v[2]); cex_asc(v[1], v[3]);
    cex_desc(v[4], v[6]); cex_desc(v[5], v[7]);
    cex_asc(v[0], v[1]); cex_asc(v[2], v[3]);
    cex_desc(v[4], v[5]); cex_desc(v[6], v[7]);
    // k=8
    {
        const bool up = ((lane & 1) == 0);
        intra_rt<4>(v, up); intra_rt<2>(v, up); intra_rt<1>(v, up);
    }
    // k=16
    {
        const bool up = ((lane & 2) == 0);
        cross<1>(v, up, lane);
        intra_rt<4>(v, up); intra_rt<2>(v, up); intra_rt<1>(v, up);
    }
    // k=32
    {
        const bool up = ((lane & 4) == 0);
        cross<2>(v, up, lane); cross<1>(v, up, lane);
        intra_rt<4>(v, up); intra_rt<2>(v, up); intra_rt<1>(v, up);
    }
    // k=64
    {
        const bool up = ((lane & 8) == 0);
        cross<4>(v, up, lane); cross<2>(v, up, lane); cross<1>(v, up, lane);
        intra_rt<4>(v, up); intra_rt<2>(v, up); intra_rt<1>(v, up);
    }
    // k=128
    {
        const bool up = ((lane & 16) == 0);
        cross<8>(v, up, lane); cross<4>(v, up, lane);
        cross<2>(v, up, lane); cross<1>(v, up, lane);
        intra_rt<4>(v, up); intra_rt<2>(v, up); intra_rt<1>(v, up);
    }
    // k=256 (final ascending merge, up == true)
    {
        const bool up = true;
        cross<16>(v, up, lane); cross<8>(v, up, lane); cross<4>(v, up, lane);
        cross<2>(v, up, lane);  cross<1>(v, up, lane);
        intra_rt<4>(v, up); intra_rt<2>(v, up); intra_rt<1>(v, up);
    }

    // ---- weighted sorted sum + mae ----
    float ws = 0.0f;
    #pragma unroll
    for (int r = 0; r < VPT; r++) {
        const float w = (float)(2 * (lane * VPT + r) - (MDIM - 1));
        ws += w * v[r];
    }
    float t = mae * c1 + ws * c2;

    // warp reduce
    #pragma unroll
    for (int off = 16; off; off >>= 1)
        t += __shfl_xor_sync(0xffffffffu, t, off);

    __shared__ float red[ROWS_PER_CTA];
    __shared__ bool  s_last;
    if (lane == 0) red[warp] = t;
    __syncthreads();

    if (threadIdx.x == 0) {
        float s = 0.0f;
        #pragma unroll
        for (int i = 0; i < ROWS_PER_CTA; i++) s += red[i];
        g_partials[blockIdx.x] = s;
        __threadfence();
        const unsigned int old = atomicAdd(&g_count, 1u);
        s_last = (old == (unsigned int)(n_ctas - 1));
    }
    __syncthreads();

    // ---- last CTA: deterministic final reduction over per-CTA partials ----
    if (s_last) {
        __threadfence();
        float acc = 0.0f;
        for (int i = threadIdx.x; i < n_ctas; i += MDIM) acc += g_partials[i];
        #pragma unroll
        for (int off = 16; off; off >>= 1)
            acc += __shfl_xor_sync(0xffffffffu, acc, off);
        if (lane == 0) red[warp] = acc;
        __syncthreads();
        if (threadIdx.x == 0) {
            float s = 0.0f;
            #pragma unroll
            for (int i = 0; i < ROWS_PER_CTA; i++) s += red[i];
            out[0] = s;
            g_count = 0;   // reset for next graph replay
        }
    }
}

extern "C" void kernel_launch(void* const* d_in, const int* in_sizes, int n_in,
                              void* d_out, int out_size)
{
    const float* y_pred = (const float*)d_in[0];
    const float* y      = (const float*)d_in[1];
    float* out          = (float*)d_out;

    const int n = in_sizes[1];             // 4096 rows
    (void)n_in; (void)out_size;

    const float c1 =  1.0f / ((float)n * (float)MDIM);
    const float c2 = -1.0f / ((float)n * (float)MDIM * (float)MDIM);

    const int n_ctas = n / ROWS_PER_CTA;   // 512
    crps_row_kernel<<<n_ctas, MDIM>>>(y_pred, y, c1, c2, out, n_ctas);
}

// round 5
// speedup vs baseline: 2.1454x; 1.0025x over previous
#include <cuda_runtime.h>

// CRPS loss: out = mean|y_pred - y| - sum_{i,k,l}|x[i,k]-x[i,l]| / (n*2*m^2)
// Sorted-row identity:  sum_{k,l}|x_k - x_l| = 2 * sum_j (2j - m + 1) x_(j)
//
// One WARP per row, 8 elements per thread (element index = lane*8 + r).
// Bitonic sort: strides 1,2,4 in-register (FMNMX), strides 8..128 via
// shfl_xor + predicated FMNMX. No __syncthreads in the sort.
// CTA = 64 threads = 2 warps = 2 rows -> grid 2048 for fine-grained SM
// packing (occupancy fix vs 256-thread CTAs). Fused last-block-done
// deterministic final reduction.

#define MDIM 256
#define VPT 8
#define WARPS_PER_CTA 2
#define ROWS_PER_CTA WARPS_PER_CTA
#define NTHREADS (WARPS_PER_CTA * 32)
#define MAX_CTAS 8192

__device__ float        g_partials[MAX_CTAS];
__device__ unsigned int g_count;   // zero-init; reset by last CTA each launch

__device__ __forceinline__ void cex_asc(float& a, float& b) {
    float mn = fminf(a, b); b = fmaxf(a, b); a = mn;
}
__device__ __forceinline__ void cex_desc(float& a, float& b) {
    float mx = fmaxf(a, b); b = fminf(a, b); a = mx;
}
__device__ __forceinline__ void cex_rt(float& a, float& b, bool asc) {
    float mn = fminf(a, b), mx = fmaxf(a, b);
    a = asc ? mn : mx;
    b = asc ? mx : mn;
}

template <int J>
__device__ __forceinline__ void intra_rt(float v[VPT], bool up) {
    #pragma unroll
    for (int r = 0; r < VPT; r++)
        if ((r & J) == 0) cex_rt(v[r], v[r | J], up);
}

template <int LM>
__device__ __forceinline__ void cross(float v[VPT], bool up, int lane) {
    const bool keep_min = (up != ((lane & LM) != 0));
    #pragma unroll
    for (int r = 0; r < VPT; r++) {
        float p = __shfl_xor_sync(0xffffffffu, v[r], LM);
        v[r] = keep_min ? fminf(v[r], p) : fmaxf(v[r], p);
    }
}

__global__ void __launch_bounds__(NTHREADS) crps_row_kernel(
    const float* __restrict__ y_pred,
    const float* __restrict__ y,
    float c1,   //  1/(n*m)
    float c2,   // -1/(n*m*m)
    float* __restrict__ out,
    int n_ctas)
{
    const int warp = threadIdx.x >> 5;
    const int lane = threadIdx.x & 31;
    const int row  = blockIdx.x * ROWS_PER_CTA + warp;

    const float4* p = (const float4*)(y_pred + row * MDIM + lane * VPT);
    const float4 a4 = p[0];
    const float4 b4 = p[1];
    float v[VPT] = {a4.x, a4.y, a4.z, a4.w, b4.x, b4.y, b4.z, b4.w};

    const float yv = __ldg(&y[row]);
    float mae = 0.0f;
    #pragma unroll
    for (int r = 0; r < VPT; r++) mae += fabsf(v[r] - yv);

    // ---- bitonic sort of 256 elements, warp-collective ----
    // k=2
    cex_asc(v[0], v[1]); cex_desc(v[2], v[3]);
    cex_asc(v[4], v[5]); cex_desc(v[6], v[7]);
    // k=4
    cex_asc(v[0], v[2]); cex_asc(v[1], v[3]);
    cex_desc(v[4], v[6]); cex_desc(v[5], v[7]);
    cex_asc(v[0], v[1]); cex_asc(v[2], v[3]);
    cex_desc(v[4], v[5]); cex_desc(v[6], v[7]);
    // k=8
    {
        const bool up = ((lane & 1) == 0);
        intra_rt<4>(v, up); intra_rt<2>(v, up); intra_rt<1>(v, up);
    }
    // k=16
    {
        const bool up = ((lane & 2) == 0);
        cross<1>(v, up, lane);
        intra_rt<4>(v, up); intra_rt<2>(v, up); intra_rt<1>(v, up);
    }
    // k=32
    {
        const bool up = ((lane & 4) == 0);
        cross<2>(v, up, lane); cross<1>(v, up, lane);
        intra_rt<4>(v, up); intra_rt<2>(v, up); intra_rt<1>(v, up);
    }
    // k=64
    {
        const bool up = ((lane & 8) == 0);
        cross<4>(v, up, lane); cross<2>(v, up, lane); cross<1>(v, up, lane);
        intra_rt<4>(v, up); intra_rt<2>(v, up); intra_rt<1>(v, up);
    }
    // k=128
    {
        const bool up = ((lane & 16) == 0);
        cross<8>(v, up, lane); cross<4>(v, up, lane);
        cross<2>(v, up, lane); cross<1>(v, up, lane);
        intra_rt<4>(v, up); intra_rt<2>(v, up); intra_rt<1>(v, up);
    }
    // k=256 (final ascending merge)
    {
        const bool up = true;
        cross<16>(v, up, lane); cross<8>(v, up, lane); cross<4>(v, up, lane);
        cross<2>(v, up, lane);  cross<1>(v, up, lane);
        intra_rt<4>(v, up); intra_rt<2>(v, up); intra_rt<1>(v, up);
    }

    // ---- weighted sorted sum + mae ----
    float ws = 0.0f;
    #pragma unroll
    for (int r = 0; r < VPT; r++) {
        const float w = (float)(2 * (lane * VPT + r) - (MDIM - 1));
        ws += w * v[r];
    }
    float t = mae * c1 + ws * c2;

    #pragma unroll
    for (int off = 16; off; off >>= 1)
        t += __shfl_xor_sync(0xffffffffu, t, off);

    __shared__ float red[WARPS_PER_CTA];
    __shared__ bool  s_last;
    if (lane == 0) red[warp] = t;
    __syncthreads();

    if (threadIdx.x == 0) {
        float s = 0.0f;
        #pragma unroll
        for (int i = 0; i < WARPS_PER_CTA; i++) s += red[i];
        g_partials[blockIdx.x] = s;
        __threadfence();
        const unsigned int old = atomicAdd(&g_count, 1u);
        s_last = (old == (unsigned int)(n_ctas - 1));
    }
    __syncthreads();

    // ---- last CTA: deterministic final reduction over per-CTA partials ----
    if (s_last) {
        __threadfence();
        float acc = 0.0f;
        for (int i = threadIdx.x; i < n_ctas; i += NTHREADS) acc += g_partials[i];
        #pragma unroll
        for (int off = 16; off; off >>= 1)
            acc += __shfl_xor_sync(0xffffffffu, acc, off);
        if (lane == 0) red[warp] = acc;
        __syncthreads();
        if (threadIdx.x == 0) {
            float s = 0.0f;
            #pragma unroll
            for (int i = 0; i < WARPS_PER_CTA; i++) s += red[i];
            out[0] = s;
            g_count = 0;   // reset for next graph replay
        }
    }
}

extern "C" void kernel_launch(void* const* d_in, const int* in_sizes, int n_in,
                              void* d_out, int out_size)
{
    const float* y_pred = (const float*)d_in[0];
    const float* y      = (const float*)d_in[1];
    float* out          = (float*)d_out;

    const int n = in_sizes[1];               // 4096 rows
    (void)n_in; (void)out_size;

    const float c1 =  1.0f / ((float)n * (float)MDIM);
    const float c2 = -1.0f / ((float)n * (float)MDIM * (float)MDIM);

    const int n_ctas = n / ROWS_PER_CTA;     // 2048
    crps_row_kernel<<<n_ctas, NTHREADS>>>(y_pred, y, c1, c2, out, n_ctas);
}